// round 1
// baseline (speedup 1.0000x reference)
#include <cuda_runtime.h>

#define AA 500000
#define CC 91
#define NCLS 90
#define KK 100
#define DD 200
#define CAP 4096
#define BINS 1024
#define BIN_BASE 15360
#define SCORE_T 0.01f
#define NMS_T 0.45f
#define NEG_INF -1e30f
#define BBOX_CLIP 4.135166556742356f
#define IMG 512.0f

// ---------------- scratch (static device globals; no allocation) ----------------
__device__ float g_amax[AA];
__device__ float g_invS[AA];
__device__ int   g_hist[NCLS * BINS];
__device__ int   g_cut[NCLS];
__device__ int   g_cnt[NCLS];
__device__ unsigned long long g_cand[NCLS * CAP];
__device__ float g_vals[NCLS * KK];
__device__ int   g_anchor[NCLS * KK];
__device__ float g_boxes[NCLS * KK * 4];
__device__ int   g_ncls[NCLS];
__device__ int   g_maxcoord;
__device__ int   g_keptK[NCLS * KK];
__device__ int   g_kc[NCLS];
__device__ int   g_selC[DD];
__device__ int   g_selK[DD];
__device__ int   g_numKept;

__device__ __forceinline__ int binOf(float p) {
    int b = (int)(__float_as_uint(p) >> 16) - BIN_BASE;
    return b < 0 ? 0 : (b > BINS - 1 ? BINS - 1 : b);
}

// ---------------- K0: zero the per-launch state (graph replays!) ----------------
__global__ void k_zero() {
    int t = blockIdx.x * blockDim.x + threadIdx.x;
    int stride = gridDim.x * blockDim.x;
    for (int i = t; i < NCLS * BINS; i += stride) g_hist[i] = 0;
    if (t < NCLS) g_cnt[t] = 0;
    if (t == NCLS) g_maxcoord = 0;
}

// ---------------- K1: softmax stats + score histogram (pass 1 over logits) ------
__global__ void k_stats(const float* __restrict__ logits) {
    int lane = threadIdx.x & 31;
    int gw = (blockIdx.x * blockDim.x + threadIdx.x) >> 5;
    int nw = (gridDim.x * blockDim.x) >> 5;
    for (int a = gw; a < AA; a += nw) {
        const float* row = logits + (size_t)a * CC;
        float z0 = row[lane];
        float z1 = row[lane + 32];
        float z2 = (lane < 27) ? row[lane + 64] : -3.4e38f;
        float m = fmaxf(fmaxf(z0, z1), z2);
#pragma unroll
        for (int o = 16; o; o >>= 1) m = fmaxf(m, __shfl_xor_sync(0xffffffffu, m, o));
        float e0 = __expf(z0 - m), e1 = __expf(z1 - m);
        float e2 = (lane < 27) ? __expf(z2 - m) : 0.f;
        float s = e0 + e1 + e2;
#pragma unroll
        for (int o = 16; o; o >>= 1) s += __shfl_xor_sync(0xffffffffu, s, o);
        float invS = __frcp_rn(s);
        if (lane == 0) { g_amax[a] = m; g_invS[a] = invS; }
        float p0 = e0 * invS;
        if (lane > 0 && p0 > SCORE_T)
            atomicAdd(&g_hist[(lane - 1) * BINS + binOf(p0)], 1);
        float p1 = e1 * invS;
        if (p1 > SCORE_T)
            atomicAdd(&g_hist[(lane + 31) * BINS + binOf(p1)], 1);
        if (lane < 27) {
            float p2 = e2 * invS;
            if (p2 > SCORE_T)
                atomicAdd(&g_hist[(lane + 63) * BINS + binOf(p2)], 1);
        }
    }
}

// ---------------- K2: per-class cutoff bin from histogram ------------------------
__global__ void k_cut() {
    int c = threadIdx.x;
    if (c < NCLS) {
        int cum = 0, cut = 0;
        for (int b = BINS - 1; b >= 0; --b) {
            cum += g_hist[c * BINS + b];
            if (cum >= KK) { cut = b; break; }
        }
        g_cut[c] = cut;
    }
}

// ---------------- K3: candidate collection (pass 2 over logits) ------------------
__global__ void k_collect(const float* __restrict__ logits) {
    __shared__ int scut[NCLS];
    if (threadIdx.x < NCLS) scut[threadIdx.x] = g_cut[threadIdx.x];
    __syncthreads();
    int lane = threadIdx.x & 31;
    int gw = (blockIdx.x * blockDim.x + threadIdx.x) >> 5;
    int nw = (gridDim.x * blockDim.x) >> 5;
    for (int a = gw; a < AA; a += nw) {
        const float* row = logits + (size_t)a * CC;
        float m = g_amax[a], invS = g_invS[a];
        float z0 = row[lane], z1 = row[lane + 32];
        if (lane > 0) {
            float p = __expf(z0 - m) * invS;
            if (p > SCORE_T) {
                int r = lane - 1;
                if (binOf(p) >= scut[r]) {
                    int pos = atomicAdd(&g_cnt[r], 1);
                    if (pos < CAP)
                        g_cand[r * CAP + pos] =
                            ((unsigned long long)__float_as_uint(p) << 32) | (unsigned)(~(unsigned)a);
                }
            }
        }
        {
            float p = __expf(z1 - m) * invS;
            if (p > SCORE_T) {
                int r = lane + 31;
                if (binOf(p) >= scut[r]) {
                    int pos = atomicAdd(&g_cnt[r], 1);
                    if (pos < CAP)
                        g_cand[r * CAP + pos] =
                            ((unsigned long long)__float_as_uint(p) << 32) | (unsigned)(~(unsigned)a);
                }
            }
        }
        if (lane < 27) {
            float z2 = row[lane + 64];
            float p = __expf(z2 - m) * invS;
            if (p > SCORE_T) {
                int r = lane + 63;
                if (binOf(p) >= scut[r]) {
                    int pos = atomicAdd(&g_cnt[r], 1);
                    if (pos < CAP)
                        g_cand[r * CAP + pos] =
                            ((unsigned long long)__float_as_uint(p) << 32) | (unsigned)(~(unsigned)a);
                }
            }
        }
    }
}

// ---------------- K4: per-class exact top-K sort + box decode/clip ---------------
__global__ void k_topk(const float* __restrict__ breg, const float* __restrict__ anchors) {
    __shared__ unsigned long long sk[CAP];   // 32 KB
    int c = blockIdx.x, tid = threadIdx.x;
    int n = g_cnt[c]; if (n > CAP) n = CAP;
    int npad = 1; while (npad < n) npad <<= 1;
    for (int i = tid; i < npad; i += blockDim.x)
        sk[i] = (i < n) ? g_cand[c * CAP + i] : 0ull;
    __syncthreads();
    // bitonic sort descending (key = score bits desc, anchor asc via ~a)
    for (int size = 2; size <= npad; size <<= 1) {
        for (int stride = size >> 1; stride > 0; stride >>= 1) {
            for (int t = tid; t < (npad >> 1); t += blockDim.x) {
                int i = ((t & ~(stride - 1)) << 1) | (t & (stride - 1));
                int j = i + stride;
                bool dsc = ((i & size) == 0);
                unsigned long long x = sk[i], y = sk[j];
                if (dsc == (x < y)) { sk[i] = y; sk[j] = x; }
            }
            __syncthreads();
        }
    }
    float localmax = 0.f;
    for (int k = tid; k < KK; k += blockDim.x) {
        float val; int a;
        if (k < n) {
            unsigned long long key = sk[k];
            val = __uint_as_float((unsigned)(key >> 32));
            a = (int)(~(unsigned)key);
        } else { val = NEG_INF; a = 0; }
        g_vals[c * KK + k] = val;
        g_anchor[c * KK + k] = a;
        float b0 = 0.f, b1 = 0.f, b2 = 0.f, b3 = 0.f;
        if (k < n) {
            float ax1 = anchors[a * 4 + 0], ay1 = anchors[a * 4 + 1];
            float ax2 = anchors[a * 4 + 2], ay2 = anchors[a * 4 + 3];
            float wa = ax2 - ax1, ha = ay2 - ay1;
            float cxa = ax1 + 0.5f * wa, cya = ay1 + 0.5f * ha;
            float r0 = breg[a * 4 + 0], r1 = breg[a * 4 + 1];
            float r2 = breg[a * 4 + 2], r3 = breg[a * 4 + 3];
            float dx = r0 / 10.0f, dy = r1 / 10.0f;
            float dw = fminf(r2 / 5.0f, BBOX_CLIP), dh = fminf(r3 / 5.0f, BBOX_CLIP);
            float cx = dx * wa + cxa, cy = dy * ha + cya;
            float w = expf(dw) * wa, h = expf(dh) * ha;
            b0 = cx - 0.5f * w; b1 = cy - 0.5f * h;
            b2 = cx + 0.5f * w; b3 = cy + 0.5f * h;
            b0 = fminf(fmaxf(b0, 0.f), IMG); b1 = fminf(fmaxf(b1, 0.f), IMG);
            b2 = fminf(fmaxf(b2, 0.f), IMG); b3 = fminf(fmaxf(b3, 0.f), IMG);
            localmax = fmaxf(localmax, fmaxf(fmaxf(b0, b1), fmaxf(b2, b3)));
        }
        g_boxes[(c * KK + k) * 4 + 0] = b0;
        g_boxes[(c * KK + k) * 4 + 1] = b1;
        g_boxes[(c * KK + k) * 4 + 2] = b2;
        g_boxes[(c * KK + k) * 4 + 3] = b3;
    }
    atomicMax(&g_maxcoord, __float_as_int(localmax));
    if (tid == 0) g_ncls[c] = n < KK ? n : KK;
}

// ---------------- K5: per-class sequential NMS (offset boxes, exact ref math) ----
__global__ void k_nms() {
    int c = blockIdx.x, lane = threadIdx.x;  // 32 threads
    __shared__ float bx[KK * 4];
    __shared__ int supp[KK];
    __shared__ int keep[KK];
    int nv = g_ncls[c];
    float M = __int_as_float(g_maxcoord);
    float off = (float)(c + 1) * (M + 1.0f);
    for (int k = lane; k < KK; k += 32) {
        bx[k * 4 + 0] = g_boxes[(c * KK + k) * 4 + 0] + off;
        bx[k * 4 + 1] = g_boxes[(c * KK + k) * 4 + 1] + off;
        bx[k * 4 + 2] = g_boxes[(c * KK + k) * 4 + 2] + off;
        bx[k * 4 + 3] = g_boxes[(c * KK + k) * 4 + 3] + off;
        supp[k] = (k < nv) ? 0 : 1;
        keep[k] = 0;
    }
    __syncwarp();
    for (int i = 0; i < KK; i++) {
        if (!supp[i]) {
            if (lane == 0) keep[i] = 1;
            float ix1 = bx[i * 4 + 0], iy1 = bx[i * 4 + 1];
            float ix2 = bx[i * 4 + 2], iy2 = bx[i * 4 + 3];
            float areai = (ix2 - ix1) * (iy2 - iy1);
            for (int j = lane; j < KK; j += 32) {
                float jx1 = bx[j * 4 + 0], jy1 = bx[j * 4 + 1];
                float jx2 = bx[j * 4 + 2], jy2 = bx[j * 4 + 3];
                float ltx = fmaxf(ix1, jx1), lty = fmaxf(iy1, jy1);
                float rbx = fminf(ix2, jx2), rby = fminf(iy2, jy2);
                float w = fmaxf(rbx - ltx, 0.f), h = fmaxf(rby - lty, 0.f);
                float inter = w * h;
                float areaj = (jx2 - jx1) * (jy2 - jy1);
                float iou = inter / fmaxf(areai + areaj - inter, 1e-9f);
                if (iou > NMS_T) supp[j] = 1;
            }
        }
        __syncwarp();
    }
    if (lane == 0) {
        int kc = 0;
        for (int k = 0; k < KK; k++)
            if (keep[k]) g_keptK[c * KK + (kc++)] = k;
        g_kc[c] = kc;
    }
}

// ---------------- K6: 90-way merge select of global top-D kept -------------------
__device__ __forceinline__ unsigned long long mergeKey(int c, int k) {
    int ci = c * KK + k;
    return ((unsigned long long)__float_as_uint(g_vals[ci]) << 32) |
           (unsigned long long)(0xFFFFFFFFu - (unsigned)ci);
}

__global__ void k_select() {
    __shared__ unsigned long long cur[NCLS];
    __shared__ int head[NCLS], kcs[NCLS];
    int lane = threadIdx.x;  // 32 threads
    int tot = 0;
    for (int c = lane; c < NCLS; c += 32) {
        int kc = g_kc[c]; kcs[c] = kc; head[c] = 0; tot += kc;
        cur[c] = (kc > 0) ? mergeKey(c, g_keptK[c * KK]) : 0ull;
    }
#pragma unroll
    for (int o = 16; o; o >>= 1) tot += __shfl_xor_sync(0xffffffffu, tot, o);
    if (lane == 0) g_numKept = tot < DD ? tot : DD;
    __syncwarp();
    for (int t = 0; t < DD; t++) {
        unsigned long long best = 0; int bc = -1;
        for (int c = lane; c < NCLS; c += 32) {
            unsigned long long v = cur[c];
            if (v > best) { best = v; bc = c; }
        }
#pragma unroll
        for (int o = 16; o; o >>= 1) {
            unsigned long long ob = __shfl_xor_sync(0xffffffffu, best, o);
            int oc = __shfl_xor_sync(0xffffffffu, bc, o);
            if (ob > best) { best = ob; bc = oc; }
        }
        if (best == 0ull) break;
        if (lane == 0) {
            int h = head[bc];
            g_selC[t] = bc;
            g_selK[t] = g_keptK[bc * KK + h];
            h++; head[bc] = h;
            cur[bc] = (h < kcs[bc]) ? mergeKey(bc, g_keptK[bc * KK + h]) : 0ull;
        }
        __syncwarp();
    }
}

// ---------------- K7: write outputs (boxes[1,0,3,2], scores, labels, logits) -----
__global__ void k_output(float* __restrict__ out, const float* __restrict__ logits) {
    int t = blockIdx.x, tid = threadIdx.x;
    int nk = g_numKept;
    if (t < nk) {
        int c = g_selC[t], k = g_selK[t], ci = c * KK + k;
        int a = g_anchor[ci];
        if (tid == 0) {
            out[t * 4 + 0] = g_boxes[ci * 4 + 1];
            out[t * 4 + 1] = g_boxes[ci * 4 + 0];
            out[t * 4 + 2] = g_boxes[ci * 4 + 3];
            out[t * 4 + 3] = g_boxes[ci * 4 + 2];
            out[DD * 4 + t] = g_vals[ci];
            out[DD * 5 + t] = (float)(c + 1);
        }
        const float* row = logits + (size_t)a * CC;
        for (int j = tid; j < CC; j += blockDim.x)
            out[DD * 6 + t * CC + j] = row[j];
    } else {
        if (tid == 0) {
            out[t * 4 + 0] = 0.f; out[t * 4 + 1] = 0.f;
            out[t * 4 + 2] = 0.f; out[t * 4 + 3] = 0.f;
            out[DD * 4 + t] = 0.f;
            out[DD * 5 + t] = 0.f;
        }
        for (int j = tid; j < CC; j += blockDim.x)
            out[DD * 6 + t * CC + j] = 0.f;
    }
}

extern "C" void kernel_launch(void* const* d_in, const int* in_sizes, int n_in,
                              void* d_out, int out_size) {
    const float* logits = (const float*)d_in[0];
    const float* breg = (const float*)d_in[1];
    const float* anchors = (const float*)d_in[2];
    float* out = (float*)d_out;

    k_zero<<<360, 256>>>();
    k_stats<<<2048, 256>>>(logits);
    k_cut<<<1, 128>>>();
    k_collect<<<2048, 256>>>(logits);
    k_topk<<<NCLS, 256>>>(breg, anchors);
    k_nms<<<NCLS, 32>>>();
    k_select<<<1, 32>>>();
    k_output<<<DD, 128>>>(out, logits);
}

// round 5
// speedup vs baseline: 1.2698x; 1.2698x over previous
#include <cuda_runtime.h>

#define AA 500000
#define CC 91
#define NCLS 90
#define KK 100
#define DD 200
#define CAP 2048
#define HBINS 80
#define HPAD 81
#define HBASE 1968   /* 123<<4 : bins cover p in [2^-4, 2) with 4 mantissa bits */
#define GATE 0.0625f
#define SCORE_T 0.01f
#define NMS_T 0.45f
#define NEG_INF -1e30f
#define BBOX_CLIP 4.135166556742356f
#define IMG 512.0f

// ---------------- scratch (static device globals; no allocation) ----------------
__device__ float g_amax[AA];
__device__ float g_invS[AA];
__device__ float g_zbase[AA];          // amax + ln(sum)
__device__ int   g_hist[NCLS * HBINS];
__device__ float g_thrC[NCLS];         // ln(edge of bin cut-1)
__device__ int   g_cnt[NCLS];
__device__ unsigned long long g_cand[NCLS * CAP];
__device__ float g_vals[NCLS * KK];
__device__ int   g_anchor[NCLS * KK];
__device__ float g_boxes[NCLS * KK * 4];
__device__ int   g_ncls[NCLS];
__device__ int   g_maxcoord;
__device__ int   g_keptK[NCLS * KK];
__device__ int   g_kc[NCLS];
__device__ int   g_selC[DD];
__device__ int   g_selK[DD];
__device__ int   g_numKept;

__device__ __forceinline__ int hbin(float p) {
    int b = (int)(__float_as_uint(p) >> 19) - HBASE;
    return b < 0 ? 0 : (b > HBINS - 1 ? HBINS - 1 : b);
}

// ---------------- K0: zero per-launch state (graph replays!) --------------------
__global__ void k_zero() {
    int t = blockIdx.x * blockDim.x + threadIdx.x;
    int stride = gridDim.x * blockDim.x;
    for (int i = t; i < NCLS * HBINS; i += stride) g_hist[i] = 0;
    if (t < NCLS) g_cnt[t] = 0;
    if (t == NCLS) g_maxcoord = 0;
}

// ---------------- K1: softmax stats + coarse smem score histogram ---------------
__global__ void k_stats(const float* __restrict__ logits) {
    __shared__ unsigned int sh[NCLS * HPAD];   // 90*81*4 = 29160 B, stride 81 (odd)
    for (int i = threadIdx.x; i < NCLS * HPAD; i += blockDim.x) sh[i] = 0u;
    __syncthreads();
    int lane = threadIdx.x & 31;
    int gw = (blockIdx.x * blockDim.x + threadIdx.x) >> 5;
    int nw = (gridDim.x * blockDim.x) >> 5;
    for (int a = gw; a < AA; a += nw) {
        const float* row = logits + (size_t)a * CC;
        float z0 = row[lane];
        float z1 = row[lane + 32];
        float z2 = (lane < 27) ? row[lane + 64] : -3.4e38f;
        float m = fmaxf(fmaxf(z0, z1), z2);
#pragma unroll
        for (int o = 16; o; o >>= 1) m = fmaxf(m, __shfl_xor_sync(0xffffffffu, m, o));
        float e0 = __expf(z0 - m), e1 = __expf(z1 - m);
        float e2 = (lane < 27) ? __expf(z2 - m) : 0.f;
        float s = e0 + e1 + e2;
#pragma unroll
        for (int o = 16; o; o >>= 1) s += __shfl_xor_sync(0xffffffffu, s, o);
        float invS = __frcp_rn(s);
        if (lane == 0) {
            g_amax[a] = m;
            g_invS[a] = invS;
            g_zbase[a] = m + __logf(s);
        }
        float p0 = e0 * invS;
        if (lane > 0 && p0 > GATE) atomicAdd(&sh[(lane - 1) * HPAD + hbin(p0)], 1u);
        float p1 = e1 * invS;
        if (p1 > GATE) atomicAdd(&sh[(lane + 31) * HPAD + hbin(p1)], 1u);
        if (lane < 27) {
            float p2 = e2 * invS;
            if (p2 > GATE) atomicAdd(&sh[(lane + 63) * HPAD + hbin(p2)], 1u);
        }
    }
    __syncthreads();
    for (int i = threadIdx.x; i < NCLS * HPAD; i += blockDim.x) {
        int b = i % HPAD;
        if (b < HBINS) {
            unsigned v = sh[i];
            if (v) atomicAdd(&g_hist[(i / HPAD) * HBINS + b], (int)v);
        }
    }
}

// ---------------- K2: per-class cutoff -> z-space collection threshold ----------
__global__ void k_cut() {
    int c = blockIdx.x;
    __shared__ int h[HBINS];
    if (threadIdx.x < HBINS) h[threadIdx.x] = g_hist[c * HBINS + threadIdx.x];
    __syncthreads();
    if (threadIdx.x == 0) {
        int cum = 0, cut = 0;
        for (int b = HBINS - 1; b >= 0; --b) {
            cum += h[b];
            if (cum >= KK) { cut = b; break; }
        }
        float thr;
        if (cut <= 0) thr = __logf(SCORE_T);   // fallback: collect all above SCORE_T
        else thr = __logf(__uint_as_float((unsigned)(cut - 1 + HBASE) << 19));
        g_thrC[c] = thr;
    }
}

// ---------------- K3: candidate collection (z-space filter, exp only on hits) ---
__global__ void k_collect(const float* __restrict__ logits) {
    __shared__ float thr[NCLS];
    if (threadIdx.x < NCLS) thr[threadIdx.x] = g_thrC[threadIdx.x];
    __syncthreads();
    int lane = threadIdx.x & 31;
    int gw = (blockIdx.x * blockDim.x + threadIdx.x) >> 5;
    int nw = (gridDim.x * blockDim.x) >> 5;
    for (int a = gw; a < AA; a += nw) {
        const float* row = logits + (size_t)a * CC;
        float base = g_zbase[a];
        float z0 = row[lane];
        float z1 = row[lane + 32];
        bool c0 = (lane > 0) && (z0 > base + thr[lane - 1]);
        bool c1 = (z1 > base + thr[lane + 31]);
        float z2 = 0.f;
        bool c2 = false;
        if (lane < 27) {
            z2 = row[lane + 64];
            c2 = (z2 > base + thr[lane + 63]);
        }
        if (c0 | c1 | c2) {
            float m = g_amax[a], invS = g_invS[a];
            if (c0) {
                float p = __expf(z0 - m) * invS;
                int r = lane - 1;
                int pos = atomicAdd(&g_cnt[r], 1);
                if (pos < CAP)
                    g_cand[r * CAP + pos] =
                        ((unsigned long long)__float_as_uint(p) << 32) | (unsigned)(~(unsigned)a);
            }
            if (c1) {
                float p = __expf(z1 - m) * invS;
                int r = lane + 31;
                int pos = atomicAdd(&g_cnt[r], 1);
                if (pos < CAP)
                    g_cand[r * CAP + pos] =
                        ((unsigned long long)__float_as_uint(p) << 32) | (unsigned)(~(unsigned)a);
            }
            if (c2) {
                float p = __expf(z2 - m) * invS;
                int r = lane + 63;
                int pos = atomicAdd(&g_cnt[r], 1);
                if (pos < CAP)
                    g_cand[r * CAP + pos] =
                        ((unsigned long long)__float_as_uint(p) << 32) | (unsigned)(~(unsigned)a);
            }
        }
    }
}

// ---------------- K4: per-class exact top-K sort + box decode/clip --------------
__global__ void k_topk(const float* __restrict__ breg, const float* __restrict__ anchors) {
    __shared__ unsigned long long sk[CAP];   // 16 KB
    int c = blockIdx.x, tid = threadIdx.x;
    int n = g_cnt[c]; if (n > CAP) n = CAP;
    int npad = 1; while (npad < n) npad <<= 1;
    for (int i = tid; i < npad; i += blockDim.x)
        sk[i] = (i < n) ? g_cand[c * CAP + i] : 0ull;
    __syncthreads();
    // bitonic sort descending (key = score bits desc, anchor asc via ~a)
    for (int size = 2; size <= npad; size <<= 1) {
        for (int stride = size >> 1; stride > 0; stride >>= 1) {
            for (int t = tid; t < (npad >> 1); t += blockDim.x) {
                int i = ((t & ~(stride - 1)) << 1) | (t & (stride - 1));
                int j = i + stride;
                bool dsc = ((i & size) == 0);
                unsigned long long x = sk[i], y = sk[j];
                if (dsc == (x < y)) { sk[i] = y; sk[j] = x; }
            }
            __syncthreads();
        }
    }
    float localmax = 0.f;
    for (int k = tid; k < KK; k += blockDim.x) {
        float val; int a;
        if (k < n) {
            unsigned long long key = sk[k];
            val = __uint_as_float((unsigned)(key >> 32));
            a = (int)(~(unsigned)key);
        } else { val = NEG_INF; a = 0; }
        g_vals[c * KK + k] = val;
        g_anchor[c * KK + k] = a;
        float b0 = 0.f, b1 = 0.f, b2 = 0.f, b3 = 0.f;
        if (k < n) {
            float ax1 = anchors[a * 4 + 0], ay1 = anchors[a * 4 + 1];
            float ax2 = anchors[a * 4 + 2], ay2 = anchors[a * 4 + 3];
            float wa = ax2 - ax1, ha = ay2 - ay1;
            float cxa = ax1 + 0.5f * wa, cya = ay1 + 0.5f * ha;
            float r0 = breg[a * 4 + 0], r1 = breg[a * 4 + 1];
            float r2 = breg[a * 4 + 2], r3 = breg[a * 4 + 3];
            float dx = r0 / 10.0f, dy = r1 / 10.0f;
            float dw = fminf(r2 / 5.0f, BBOX_CLIP), dh = fminf(r3 / 5.0f, BBOX_CLIP);
            float cx = dx * wa + cxa, cy = dy * ha + cya;
            float w = expf(dw) * wa, h = expf(dh) * ha;
            b0 = cx - 0.5f * w; b1 = cy - 0.5f * h;
            b2 = cx + 0.5f * w; b3 = cy + 0.5f * h;
            b0 = fminf(fmaxf(b0, 0.f), IMG); b1 = fminf(fmaxf(b1, 0.f), IMG);
            b2 = fminf(fmaxf(b2, 0.f), IMG); b3 = fminf(fmaxf(b3, 0.f), IMG);
            localmax = fmaxf(localmax, fmaxf(fmaxf(b0, b1), fmaxf(b2, b3)));
        }
        g_boxes[(c * KK + k) * 4 + 0] = b0;
        g_boxes[(c * KK + k) * 4 + 1] = b1;
        g_boxes[(c * KK + k) * 4 + 2] = b2;
        g_boxes[(c * KK + k) * 4 + 3] = b3;
    }
    atomicMax(&g_maxcoord, __float_as_int(localmax));
    if (tid == 0) g_ncls[c] = n < KK ? n : KK;
}

// ---------------- K5: per-class sequential NMS (offset boxes, exact ref math) ---
__global__ void k_nms() {
    int c = blockIdx.x, lane = threadIdx.x;  // 32 threads
    __shared__ float bx[KK * 4];
    __shared__ int supp[KK];
    __shared__ int keep[KK];
    int nv = g_ncls[c];
    float M = __int_as_float(g_maxcoord);
    float off = (float)(c + 1) * (M + 1.0f);
    for (int k = lane; k < KK; k += 32) {
        bx[k * 4 + 0] = g_boxes[(c * KK + k) * 4 + 0] + off;
        bx[k * 4 + 1] = g_boxes[(c * KK + k) * 4 + 1] + off;
        bx[k * 4 + 2] = g_boxes[(c * KK + k) * 4 + 2] + off;
        bx[k * 4 + 3] = g_boxes[(c * KK + k) * 4 + 3] + off;
        supp[k] = (k < nv) ? 0 : 1;
        keep[k] = 0;
    }
    __syncwarp();
    for (int i = 0; i < KK; i++) {
        if (!supp[i]) {
            if (lane == 0) keep[i] = 1;
            float ix1 = bx[i * 4 + 0], iy1 = bx[i * 4 + 1];
            float ix2 = bx[i * 4 + 2], iy2 = bx[i * 4 + 3];
            float areai = (ix2 - ix1) * (iy2 - iy1);
            for (int j = lane; j < KK; j += 32) {
                float jx1 = bx[j * 4 + 0], jy1 = bx[j * 4 + 1];
                float jx2 = bx[j * 4 + 2], jy2 = bx[j * 4 + 3];
                float ltx = fmaxf(ix1, jx1), lty = fmaxf(iy1, jy1);
                float rbx = fminf(ix2, jx2), rby = fminf(iy2, jy2);
                float w = fmaxf(rbx - ltx, 0.f), h = fmaxf(rby - lty, 0.f);
                float inter = w * h;
                float areaj = (jx2 - jx1) * (jy2 - jy1);
                float iou = inter / fmaxf(areai + areaj - inter, 1e-9f);
                if (iou > NMS_T) supp[j] = 1;
            }
        }
        __syncwarp();
    }
    if (lane == 0) {
        int kc = 0;
        for (int k = 0; k < KK; k++)
            if (keep[k]) g_keptK[c * KK + (kc++)] = k;
        g_kc[c] = kc;
    }
}

// ---------------- K6: 90-way merge select of global top-D kept ------------------
__device__ __forceinline__ unsigned long long mergeKey(int c, int k) {
    int ci = c * KK + k;
    return ((unsigned long long)__float_as_uint(g_vals[ci]) << 32) |
           (unsigned long long)(0xFFFFFFFFu - (unsigned)ci);
}

__global__ void k_select() {
    __shared__ unsigned long long cur[NCLS];
    __shared__ int head[NCLS], kcs[NCLS];
    int lane = threadIdx.x;  // 32 threads
    int tot = 0;
    for (int c = lane; c < NCLS; c += 32) {
        int kc = g_kc[c]; kcs[c] = kc; head[c] = 0; tot += kc;
        cur[c] = (kc > 0) ? mergeKey(c, g_keptK[c * KK]) : 0ull;
    }
#pragma unroll
    for (int o = 16; o; o >>= 1) tot += __shfl_xor_sync(0xffffffffu, tot, o);
    if (lane == 0) g_numKept = tot < DD ? tot : DD;
    __syncwarp();
    for (int t = 0; t < DD; t++) {
        unsigned long long best = 0; int bc = -1;
        for (int c = lane; c < NCLS; c += 32) {
            unsigned long long v = cur[c];
            if (v > best) { best = v; bc = c; }
        }
#pragma unroll
        for (int o = 16; o; o >>= 1) {
            unsigned long long ob = __shfl_xor_sync(0xffffffffu, best, o);
            int oc = __shfl_xor_sync(0xffffffffu, bc, o);
            if (ob > best) { best = ob; bc = oc; }
        }
        if (best == 0ull) break;
        if (lane == 0) {
            int h = head[bc];
            g_selC[t] = bc;
            g_selK[t] = g_keptK[bc * KK + h];
            h++; head[bc] = h;
            cur[bc] = (h < kcs[bc]) ? mergeKey(bc, g_keptK[bc * KK + h]) : 0ull;
        }
        __syncwarp();
    }
}

// ---------------- K7: write outputs ---------------------------------------------
__global__ void k_output(float* __restrict__ out, const float* __restrict__ logits) {
    int t = blockIdx.x, tid = threadIdx.x;
    int nk = g_numKept;
    if (t < nk) {
        int c = g_selC[t], k = g_selK[t], ci = c * KK + k;
        int a = g_anchor[ci];
        if (tid == 0) {
            out[t * 4 + 0] = g_boxes[ci * 4 + 1];
            out[t * 4 + 1] = g_boxes[ci * 4 + 0];
            out[t * 4 + 2] = g_boxes[ci * 4 + 3];
            out[t * 4 + 3] = g_boxes[ci * 4 + 2];
            out[DD * 4 + t] = g_vals[ci];
            out[DD * 5 + t] = (float)(c + 1);
        }
        const float* row = logits + (size_t)a * CC;
        for (int j = tid; j < CC; j += blockDim.x)
            out[DD * 6 + t * CC + j] = row[j];
    } else {
        if (tid == 0) {
            out[t * 4 + 0] = 0.f; out[t * 4 + 1] = 0.f;
            out[t * 4 + 2] = 0.f; out[t * 4 + 3] = 0.f;
            out[DD * 4 + t] = 0.f;
            out[DD * 5 + t] = 0.f;
        }
        for (int j = tid; j < CC; j += blockDim.x)
            out[DD * 6 + t * CC + j] = 0.f;
    }
}

extern "C" void kernel_launch(void* const* d_in, const int* in_sizes, int n_in,
                              void* d_out, int out_size) {
    const float* logits = (const float*)d_in[0];
    const float* breg = (const float*)d_in[1];
    const float* anchors = (const float*)d_in[2];
    float* out = (float*)d_out;

    k_zero<<<32, 256>>>();
    k_stats<<<512, 256>>>(logits);
    k_cut<<<NCLS, 128>>>();
    k_collect<<<2048, 256>>>(logits);
    k_topk<<<NCLS, 256>>>(breg, anchors);
    k_nms<<<NCLS, 32>>>();
    k_select<<<1, 32>>>();
    k_output<<<DD, 128>>>(out, logits);
}

// round 7
// speedup vs baseline: 1.5596x; 1.2282x over previous
#include <cuda_runtime.h>

#define AA 500000
#define CC 91
#define NCLS 90
#define KK 100
#define DD 200
#define CAP 2048
#define HBINS 80
#define HPAD 81
#define HBASE 1968   /* 123<<4 : bins cover p in [2^-4, 2) with 4 mantissa bits */
#define GATE 0.0625f
#define SBINS 1024
#define SBASE 15360  /* select histogram: float bits >> 16 */
#define SCORE_T 0.01f
#define NMS_T 0.45f
#define NEG_INF -1e30f
#define BBOX_CLIP 4.135166556742356f
#define IMG 512.0f

// ---------------- scratch (static device globals; no allocation) ----------------
__device__ float g_invS[AA];
__device__ float g_zbase[AA];          // ln(sum(exp(z)))
__device__ int   g_hist[NCLS * HBINS];
__device__ float g_thrC[NCLS];         // ln(edge of bin cut-1)
__device__ int   g_cnt[NCLS];
__device__ unsigned long long g_cand[NCLS * CAP];
__device__ float g_vals[NCLS * KK];
__device__ int   g_anchor[NCLS * KK];
__device__ float g_boxes[NCLS * KK * 4];
__device__ int   g_ncls[NCLS];
__device__ int   g_maxcoord;
__device__ int   g_keptK[NCLS * KK];
__device__ int   g_kc[NCLS];

__device__ __forceinline__ int hbin(float p) {
    int b = (int)(__float_as_uint(p) >> 19) - HBASE;
    return b < 0 ? 0 : (b > HBINS - 1 ? HBINS - 1 : b);
}

// ---------------- K0: zero per-launch state (graph replays!) --------------------
__global__ void k_zero() {
    int t = blockIdx.x * blockDim.x + threadIdx.x;
    int stride = gridDim.x * blockDim.x;
    for (int i = t; i < NCLS * HBINS; i += stride) g_hist[i] = 0;
    if (t < NCLS) g_cnt[t] = 0;
    if (t == NCLS) g_maxcoord = 0;
}

// ---------------- K1: softmax stats (no max-sub) + coarse smem histogram --------
__global__ void k_stats(const float* __restrict__ logits) {
    __shared__ unsigned int sh[NCLS * HPAD];   // stride 81 (odd) -> conflict-free
    for (int i = threadIdx.x; i < NCLS * HPAD; i += blockDim.x) sh[i] = 0u;
    __syncthreads();
    int lane = threadIdx.x & 31;
    int gw = (blockIdx.x * blockDim.x + threadIdx.x) >> 5;
    int nw = (gridDim.x * blockDim.x) >> 5;
#pragma unroll 2
    for (int a = gw; a < AA; a += nw) {
        const float* row = logits + (size_t)a * CC;
        float z0 = row[lane];
        float z1 = row[lane + 32];
        float e2 = 0.f, p2gate = 0.f;
        float e0 = __expf(z0), e1 = __expf(z1);
        if (lane < 27) e2 = __expf(row[lane + 64]);
        float s = e0 + e1 + e2;
#pragma unroll
        for (int o = 16; o; o >>= 1) s += __shfl_xor_sync(0xffffffffu, s, o);
        float invS = __frcp_rn(s);
        if (lane == 0) {
            g_invS[a] = invS;
            g_zbase[a] = __logf(s);
        }
        float p0 = e0 * invS;
        if (lane > 0 && p0 > GATE) atomicAdd(&sh[(lane - 1) * HPAD + hbin(p0)], 1u);
        float p1 = e1 * invS;
        if (p1 > GATE) atomicAdd(&sh[(lane + 31) * HPAD + hbin(p1)], 1u);
        p2gate = e2 * invS;
        if (p2gate > GATE) atomicAdd(&sh[(lane + 63) * HPAD + hbin(p2gate)], 1u);
    }
    __syncthreads();
    for (int i = threadIdx.x; i < NCLS * HPAD; i += blockDim.x) {
        int b = i % HPAD;
        if (b < HBINS) {
            unsigned v = sh[i];
            if (v) atomicAdd(&g_hist[(i / HPAD) * HBINS + b], (int)v);
        }
    }
}

// ---------------- K2: per-class cutoff -> z-space collection threshold ----------
__global__ void k_cut() {
    int c = blockIdx.x;
    __shared__ int h[HBINS];
    if (threadIdx.x < HBINS) h[threadIdx.x] = g_hist[c * HBINS + threadIdx.x];
    __syncthreads();
    if (threadIdx.x == 0) {
        int cum = 0, cut = 0;
        for (int b = HBINS - 1; b >= 0; --b) {
            cum += h[b];
            if (cum >= KK) { cut = b; break; }
        }
        float thr;
        if (cut <= 0) thr = __logf(SCORE_T);
        else thr = __logf(__uint_as_float((unsigned)(cut - 1 + HBASE) << 19));
        g_thrC[c] = thr;
    }
}

// ---------------- K3: candidate collection (z filter; exp only on hits) ---------
__global__ void k_collect(const float* __restrict__ logits) {
    __shared__ float thr[NCLS];
    if (threadIdx.x < NCLS) thr[threadIdx.x] = g_thrC[threadIdx.x];
    __syncthreads();
    int lane = threadIdx.x & 31;
    int gw = (blockIdx.x * blockDim.x + threadIdx.x) >> 5;
    int nw = (gridDim.x * blockDim.x) >> 5;
    float t0 = (lane > 0) ? thr[lane - 1] : 3.4e38f;
    float t1 = thr[lane + 31];
    float t2 = (lane < 27) ? thr[lane + 63] : 3.4e38f;
#pragma unroll 2
    for (int a = gw; a < AA; a += nw) {
        const float* row = logits + (size_t)a * CC;
        float base = g_zbase[a];
        float z0 = row[lane];
        float z1 = row[lane + 32];
        float z2 = (lane < 27) ? row[lane + 64] : -3.4e38f;
        bool c0 = z0 > base + t0;
        bool c1 = z1 > base + t1;
        bool c2 = z2 > base + t2;
        if (c0 | c1 | c2) {
            float invS = g_invS[a];
            if (c0) {
                float p = __expf(z0) * invS;
                int r = lane - 1;
                int pos = atomicAdd(&g_cnt[r], 1);
                if (pos < CAP)
                    g_cand[r * CAP + pos] =
                        ((unsigned long long)__float_as_uint(p) << 32) | (unsigned)(~(unsigned)a);
            }
            if (c1) {
                float p = __expf(z1) * invS;
                int r = lane + 31;
                int pos = atomicAdd(&g_cnt[r], 1);
                if (pos < CAP)
                    g_cand[r * CAP + pos] =
                        ((unsigned long long)__float_as_uint(p) << 32) | (unsigned)(~(unsigned)a);
            }
            if (c2) {
                float p = __expf(z2) * invS;
                int r = lane + 63;
                int pos = atomicAdd(&g_cnt[r], 1);
                if (pos < CAP)
                    g_cand[r * CAP + pos] =
                        ((unsigned long long)__float_as_uint(p) << 32) | (unsigned)(~(unsigned)a);
            }
        }
    }
}

// ---------------- K4: per-class exact top-K sort + box decode/clip --------------
__global__ void k_topk(const float* __restrict__ breg, const float* __restrict__ anchors) {
    __shared__ unsigned long long sk[CAP];   // 16 KB
    int c = blockIdx.x, tid = threadIdx.x;
    int n = g_cnt[c]; if (n > CAP) n = CAP;
    int npad = 1; while (npad < n) npad <<= 1;
    for (int i = tid; i < npad; i += blockDim.x)
        sk[i] = (i < n) ? g_cand[c * CAP + i] : 0ull;
    __syncthreads();
    for (int size = 2; size <= npad; size <<= 1) {
        for (int stride = size >> 1; stride > 0; stride >>= 1) {
            for (int t = tid; t < (npad >> 1); t += blockDim.x) {
                int i = ((t & ~(stride - 1)) << 1) | (t & (stride - 1));
                int j = i + stride;
                bool dsc = ((i & size) == 0);
                unsigned long long x = sk[i], y = sk[j];
                if (dsc == (x < y)) { sk[i] = y; sk[j] = x; }
            }
            __syncthreads();
        }
    }
    float localmax = 0.f;
    for (int k = tid; k < KK; k += blockDim.x) {
        float val; int a;
        if (k < n) {
            unsigned long long key = sk[k];
            val = __uint_as_float((unsigned)(key >> 32));
            a = (int)(~(unsigned)key);
        } else { val = NEG_INF; a = 0; }
        g_vals[c * KK + k] = val;
        g_anchor[c * KK + k] = a;
        float b0 = 0.f, b1 = 0.f, b2 = 0.f, b3 = 0.f;
        if (k < n) {
            float ax1 = anchors[a * 4 + 0], ay1 = anchors[a * 4 + 1];
            float ax2 = anchors[a * 4 + 2], ay2 = anchors[a * 4 + 3];
            float wa = ax2 - ax1, ha = ay2 - ay1;
            float cxa = ax1 + 0.5f * wa, cya = ay1 + 0.5f * ha;
            float r0 = breg[a * 4 + 0], r1 = breg[a * 4 + 1];
            float r2 = breg[a * 4 + 2], r3 = breg[a * 4 + 3];
            float dx = r0 / 10.0f, dy = r1 / 10.0f;
            float dw = fminf(r2 / 5.0f, BBOX_CLIP), dh = fminf(r3 / 5.0f, BBOX_CLIP);
            float cx = dx * wa + cxa, cy = dy * ha + cya;
            float w = expf(dw) * wa, h = expf(dh) * ha;
            b0 = cx - 0.5f * w; b1 = cy - 0.5f * h;
            b2 = cx + 0.5f * w; b3 = cy + 0.5f * h;
            b0 = fminf(fmaxf(b0, 0.f), IMG); b1 = fminf(fmaxf(b1, 0.f), IMG);
            b2 = fminf(fmaxf(b2, 0.f), IMG); b3 = fminf(fmaxf(b3, 0.f), IMG);
            localmax = fmaxf(localmax, fmaxf(fmaxf(b0, b1), fmaxf(b2, b3)));
        }
        g_boxes[(c * KK + k) * 4 + 0] = b0;
        g_boxes[(c * KK + k) * 4 + 1] = b1;
        g_boxes[(c * KK + k) * 4 + 2] = b2;
        g_boxes[(c * KK + k) * 4 + 3] = b3;
    }
    atomicMax(&g_maxcoord, __float_as_int(localmax));
    if (tid == 0) g_ncls[c] = n < KK ? n : KK;
}

// ---------------- K5: per-class sequential NMS (offset boxes, exact ref math) ---
__global__ void k_nms() {
    int c = blockIdx.x, lane = threadIdx.x;  // 32 threads
    __shared__ float bx[KK * 4];
    __shared__ int supp[KK];
    __shared__ int keep[KK];
    int nv = g_ncls[c];
    float M = __int_as_float(g_maxcoord);
    float off = (float)(c + 1) * (M + 1.0f);
    for (int k = lane; k < KK; k += 32) {
        bx[k * 4 + 0] = g_boxes[(c * KK + k) * 4 + 0] + off;
        bx[k * 4 + 1] = g_boxes[(c * KK + k) * 4 + 1] + off;
        bx[k * 4 + 2] = g_boxes[(c * KK + k) * 4 + 2] + off;
        bx[k * 4 + 3] = g_boxes[(c * KK + k) * 4 + 3] + off;
        supp[k] = (k < nv) ? 0 : 1;
        keep[k] = 0;
    }
    __syncwarp();
    for (int i = 0; i < KK; i++) {
        if (!supp[i]) {
            if (lane == 0) keep[i] = 1;
            float ix1 = bx[i * 4 + 0], iy1 = bx[i * 4 + 1];
            float ix2 = bx[i * 4 + 2], iy2 = bx[i * 4 + 3];
            float areai = (ix2 - ix1) * (iy2 - iy1);
            for (int j = lane; j < KK; j += 32) {
                float jx1 = bx[j * 4 + 0], jy1 = bx[j * 4 + 1];
                float jx2 = bx[j * 4 + 2], jy2 = bx[j * 4 + 3];
                float ltx = fmaxf(ix1, jx1), lty = fmaxf(iy1, jy1);
                float rbx = fminf(ix2, jx2), rby = fminf(iy2, jy2);
                float w = fmaxf(rbx - ltx, 0.f), h = fmaxf(rby - lty, 0.f);
                float inter = w * h;
                float areaj = (jx2 - jx1) * (jy2 - jy1);
                float iou = inter / fmaxf(areai + areaj - inter, 1e-9f);
                if (iou > NMS_T) supp[j] = 1;
            }
        }
        __syncwarp();
    }
    if (lane == 0) {
        int kc = 0;
        for (int k = 0; k < KK; k++)
            if (keep[k]) g_keptK[c * KK + (kc++)] = k;
        g_kc[c] = kc;
    }
}

// ---------------- K6: fused global top-D select + output write ------------------
__global__ void k_final(float* __restrict__ out, const float* __restrict__ logits) {
    __shared__ int sPref[NCLS + 1];
    __shared__ int sHist[SBINS];
    __shared__ unsigned long long sKeys[1024];
    __shared__ int sA[DD];
    __shared__ int sCnt, sB, sNum;
    int tid = threadIdx.x;  // 256
    for (int i = tid; i < SBINS; i += 256) sHist[i] = 0;
    if (tid == 0) {
        int acc = 0;
        for (int c = 0; c < NCLS; c++) { sPref[c] = acc; acc += g_kc[c]; }
        sPref[NCLS] = acc;
        sCnt = 0;
    }
    __syncthreads();
    int tot = sPref[NCLS];
    // pass 1: histogram of kept scores
    for (int g = tid; g < tot; g += 256) {
        int lo = 0, hi = NCLS;
        while (hi - lo > 1) { int mid = (lo + hi) >> 1; if (sPref[mid] <= g) lo = mid; else hi = mid; }
        int c = lo, j = g - sPref[c];
        int k = g_keptK[c * KK + j];
        unsigned v = __float_as_uint(g_vals[c * KK + k]);
        int b = (int)(v >> 16) - SBASE;
        b = b < 0 ? 0 : (b > SBINS - 1 ? SBINS - 1 : b);
        atomicAdd(&sHist[b], 1);
    }
    __syncthreads();
    int r = tot < DD ? tot : DD;
    if (tid == 0) {
        int cum = 0, b = 0;
        for (int i = SBINS - 1; i >= 0; --i) { cum += sHist[i]; if (cum >= r) { b = i; break; } }
        sB = (r > 0) ? b : SBINS;
        sNum = r;
    }
    __syncthreads();
    int bstar = sB;
    // pass 2: collect keys at/above cutoff bin
    for (int g = tid; g < tot; g += 256) {
        int lo = 0, hi = NCLS;
        while (hi - lo > 1) { int mid = (lo + hi) >> 1; if (sPref[mid] <= g) lo = mid; else hi = mid; }
        int c = lo, j = g - sPref[c];
        int k = g_keptK[c * KK + j];
        int ci = c * KK + k;
        unsigned v = __float_as_uint(g_vals[ci]);
        int b = (int)(v >> 16) - SBASE;
        b = b < 0 ? 0 : (b > SBINS - 1 ? SBINS - 1 : b);
        if (b >= bstar) {
            int pos = atomicAdd(&sCnt, 1);
            if (pos < 1024)
                sKeys[pos] = ((unsigned long long)v << 32) |
                             (unsigned long long)(0xFFFFFFFFu - (unsigned)ci);
        }
    }
    __syncthreads();
    int cnt = sCnt; if (cnt > 1024) cnt = 1024;
    for (int i = tid; i < 1024; i += 256) if (i >= cnt) sKeys[i] = 0ull;
    __syncthreads();
    // bitonic sort desc over 1024
    for (int size = 2; size <= 1024; size <<= 1) {
        for (int stride = size >> 1; stride > 0; stride >>= 1) {
            for (int t = tid; t < 512; t += 256) {
                int i = ((t & ~(stride - 1)) << 1) | (t & (stride - 1));
                int j = i + stride;
                bool dsc = ((i & size) == 0);
                unsigned long long x = sKeys[i], y = sKeys[j];
                if (dsc == (x < y)) { sKeys[i] = y; sKeys[j] = x; }
            }
            __syncthreads();
        }
    }
    int num = sNum;
    // outputs: boxes (swapped), scores, labels
    for (int t = tid; t < DD; t += 256) {
        if (t < num) {
            unsigned long long key = sKeys[t];
            int ci = (int)(0xFFFFFFFFu - (unsigned)key);
            int c = ci / KK;
            sA[t] = g_anchor[ci];
            out[t * 4 + 0] = g_boxes[ci * 4 + 1];
            out[t * 4 + 1] = g_boxes[ci * 4 + 0];
            out[t * 4 + 2] = g_boxes[ci * 4 + 3];
            out[t * 4 + 3] = g_boxes[ci * 4 + 2];
            out[DD * 4 + t] = __uint_as_float((unsigned)(key >> 32));
            out[DD * 5 + t] = (float)(c + 1);
        } else {
            sA[t] = -1;
            out[t * 4 + 0] = 0.f; out[t * 4 + 1] = 0.f;
            out[t * 4 + 2] = 0.f; out[t * 4 + 3] = 0.f;
            out[DD * 4 + t] = 0.f;
            out[DD * 5 + t] = 0.f;
        }
    }
    __syncthreads();
    // logit gather
    for (int idx = tid; idx < DD * CC; idx += 256) {
        int t = idx / CC, j = idx - t * CC;
        int a = sA[t];
        out[DD * 6 + idx] = (a >= 0) ? logits[(size_t)a * CC + j] : 0.f;
    }
}

extern "C" void kernel_launch(void* const* d_in, const int* in_sizes, int n_in,
                              void* d_out, int out_size) {
    const float* logits = (const float*)d_in[0];
    const float* breg = (const float*)d_in[1];
    const float* anchors = (const float*)d_in[2];
    float* out = (float*)d_out;

    k_zero<<<32, 256>>>();
    k_stats<<<1024, 256>>>(logits);
    k_cut<<<NCLS, 128>>>();
    k_collect<<<2048, 256>>>(logits);
    k_topk<<<NCLS, 256>>>(breg, anchors);
    k_nms<<<NCLS, 32>>>();
    k_final<<<1, 256>>>(out, logits);
}